// round 2
// baseline (speedup 1.0000x reference)
#include <cuda_runtime.h>
#include <cstdint>
#include <cstddef>

#define NN   50000
#define EE   800000
#define DIN  128
#define DH   256

// ---------------- scratch (device globals; no allocation allowed) ------------
__device__ float g_dinv[NN];            // deg -> dinv in place
__device__ float g_agg1[NN * DIN];      // A @ x
__device__ float g_h[(size_t)NN * DH];  // relu(agg1 @ W1^T + b1)
__device__ float g_p[NN * DIN];         // h @ W2^T (no bias)
__device__ float g_agg2[NN * DIN];      // A @ p
__device__ int   g_src[EE];             // clean int32 src ids
__device__ int   g_dst[EE];             // clean int32 dst ids
__device__ int   g_is64;                // 1 if edge_index buffer is int64

// ---------------- dtype sniffer + index conversion ---------------------------
// If edge_index is int64 (little-endian), the odd int32 words are the high
// halves of indices < 50000 -> all zero. Genuine int32 index data can't have
// 128 consecutive odd positions all zero (prob ~ (2e-5)^128).
__global__ void detect_idx_kernel(const int* __restrict__ raw) {
    __shared__ int nz;
    if (threadIdx.x == 0) nz = 0;
    __syncthreads();
    if (raw[2 * threadIdx.x + 1] != 0) atomicOr(&nz, 1);
    __syncthreads();
    if (threadIdx.x == 0) g_is64 = (nz == 0) ? 1 : 0;
}

__global__ void convert_idx_kernel(const void* __restrict__ raw,
                                   int* __restrict__ src,
                                   int* __restrict__ dst, int e) {
    int i = blockIdx.x * blockDim.x + threadIdx.x;
    if (i >= e) return;
    if (g_is64) {
        const long long* p = (const long long*)raw;
        src[i] = (int)p[i];
        dst[i] = (int)p[(size_t)e + i];
    } else {
        const int* p = (const int*)raw;
        src[i] = p[i];
        dst[i] = p[e + i];
    }
}

// ---------------- degree / normalization ------------------------------------
__global__ void init_deg_kernel(float* deg, int n) {
    int i = blockIdx.x * blockDim.x + threadIdx.x;
    if (i < n) deg[i] = 1.0f;   // self-loop weight 1.0
}

__global__ void deg_accum_kernel(const int* __restrict__ dst,
                                 const float* __restrict__ w,
                                 float* deg, int e) {
    int i = blockIdx.x * blockDim.x + threadIdx.x;
    if (i < e) atomicAdd(&deg[dst[i]], w[i]);
}

__global__ void dinv_kernel(float* deg, int n) {
    int i = blockIdx.x * blockDim.x + threadIdx.x;
    if (i < n) {
        float d = deg[i];
        deg[i] = (d > 0.f) ? rsqrtf(d) : 0.f;
    }
}

// ---------------- self-loop init (also serves as zero-init of agg) -----------
// agg[i][:] = feat[i][:] * dinv[i]^2
__global__ void selfloop_init_kernel(const float* __restrict__ feat,
                                     const float* __restrict__ dinv,
                                     float* __restrict__ agg, int total) {
    int i = blockIdx.x * blockDim.x + threadIdx.x;
    if (i < total) {
        int node = i >> 7;   // DIN = 128
        float dv = dinv[node];
        agg[i] = feat[i] * dv * dv;
    }
}

// ---------------- edge scatter: one warp per edge, 128-wide ------------------
__global__ void edge_scatter_kernel(const int* __restrict__ srcA,
                                    const int* __restrict__ dstA,
                                    const float* __restrict__ w,
                                    const float* __restrict__ dinv,
                                    const float* __restrict__ feat,
                                    float* __restrict__ agg, int e) {
    int gw   = (blockIdx.x * blockDim.x + threadIdx.x) >> 5;
    int lane = threadIdx.x & 31;
    if (gw >= e) return;

    int s = srcA[gw];
    int d = dstA[gw];
    float nrm = dinv[s] * w[gw] * dinv[d];

    float4 v = *(const float4*)(feat + (size_t)s * DIN + lane * 4);
    float* out = agg + (size_t)d * DIN + lane * 4;
    asm volatile("red.global.add.v4.f32 [%0], {%1, %2, %3, %4};"
                 :: "l"(out), "f"(v.x * nrm), "f"(v.y * nrm),
                    "f"(v.z * nrm), "f"(v.w * nrm)
                 : "memory");
}

// ---------------- fp32 SIMT GEMM: C[m][n] = sum_k A[m][k] * W[n][k] ----------
// A: [M,K] row-major (K contiguous), W: [Nout,K] row-major. BM=128 BN=64 BK=16
__global__ __launch_bounds__(256)
void gemm_tn_kernel(const float* __restrict__ A, const float* __restrict__ W,
                    const float* __restrict__ bias, float* __restrict__ C,
                    int M, int K, int Nout, int doRelu) {
    constexpr int BM = 128, BN = 64, BK = 16, TM = 8, TN = 4;
    __shared__ float As[BM][BK + 1];
    __shared__ float Ws[BN][BK + 1];

    const int tid = threadIdx.x;
    const int tx  = tid & 15;   // 16 column groups
    const int ty  = tid >> 4;   // 16 row groups
    const int m0  = blockIdx.x * BM;
    const int n0  = blockIdx.y * BN;

    float acc[TM][TN];
#pragma unroll
    for (int i = 0; i < TM; i++)
#pragma unroll
        for (int j = 0; j < TN; j++) acc[i][j] = 0.f;

    for (int k0 = 0; k0 < K; k0 += BK) {
        // A tile: 128x16 = 512 float4, 2 per thread
#pragma unroll
        for (int l = 0; l < 2; l++) {
            int idx = tid + l * 256;
            int r = idx >> 2;
            int kq = idx & 3;
            float4 v = make_float4(0.f, 0.f, 0.f, 0.f);
            int gr = m0 + r;
            if (gr < M) v = *(const float4*)(A + (size_t)gr * K + k0 + kq * 4);
            As[r][kq * 4 + 0] = v.x; As[r][kq * 4 + 1] = v.y;
            As[r][kq * 4 + 2] = v.z; As[r][kq * 4 + 3] = v.w;
        }
        // W tile: 64x16 = 256 float4, 1 per thread (Nout % BN == 0, always valid)
        {
            int r = tid >> 2;
            int kq = tid & 3;
            float4 v = *(const float4*)(W + (size_t)(n0 + r) * K + k0 + kq * 4);
            Ws[r][kq * 4 + 0] = v.x; Ws[r][kq * 4 + 1] = v.y;
            Ws[r][kq * 4 + 2] = v.z; Ws[r][kq * 4 + 3] = v.w;
        }
        __syncthreads();

#pragma unroll
        for (int k = 0; k < BK; k++) {
            float a[TM], b[TN];
#pragma unroll
            for (int i = 0; i < TM; i++) a[i] = As[ty * TM + i][k];
#pragma unroll
            for (int j = 0; j < TN; j++) b[j] = Ws[tx * TN + j][k];
#pragma unroll
            for (int i = 0; i < TM; i++)
#pragma unroll
                for (int j = 0; j < TN; j++)
                    acc[i][j] = fmaf(a[i], b[j], acc[i][j]);
        }
        __syncthreads();
    }

#pragma unroll
    for (int i = 0; i < TM; i++) {
        int row = m0 + ty * TM + i;
        if (row < M) {
            int col0 = n0 + tx * TN;
            float4 v;
            v.x = acc[i][0]; v.y = acc[i][1]; v.z = acc[i][2]; v.w = acc[i][3];
            if (bias) {
                const float4 bb = *(const float4*)(bias + col0);
                v.x += bb.x; v.y += bb.y; v.z += bb.z; v.w += bb.w;
            }
            if (doRelu) {
                v.x = fmaxf(v.x, 0.f); v.y = fmaxf(v.y, 0.f);
                v.z = fmaxf(v.z, 0.f); v.w = fmaxf(v.w, 0.f);
            }
            *(float4*)(C + (size_t)row * Nout + col0) = v;
        }
    }
}

// ---------------- LayerNorm (+ bias b2): one warp per row --------------------
__global__ void ln_kernel(const float* __restrict__ agg2,
                          const float* __restrict__ b2,
                          const float* __restrict__ gamma,
                          const float* __restrict__ beta,
                          float* __restrict__ out, int n) {
    int row  = (blockIdx.x * blockDim.x + threadIdx.x) >> 5;
    int lane = threadIdx.x & 31;
    if (row >= n) return;

    float4 v  = *(const float4*)(agg2 + (size_t)row * DIN + lane * 4);
    float4 bb = *(const float4*)(b2 + lane * 4);
    v.x += bb.x; v.y += bb.y; v.z += bb.z; v.w += bb.w;

    float s = v.x + v.y + v.z + v.w;
#pragma unroll
    for (int o = 16; o > 0; o >>= 1) s += __shfl_xor_sync(0xFFFFFFFFu, s, o);
    float mu = s * (1.0f / DIN);

    float dx = v.x - mu, dy = v.y - mu, dz = v.z - mu, dw = v.w - mu;
    float q = dx * dx + dy * dy + dz * dz + dw * dw;
#pragma unroll
    for (int o = 16; o > 0; o >>= 1) q += __shfl_xor_sync(0xFFFFFFFFu, q, o);
    float rstd = rsqrtf(q * (1.0f / DIN) + 1e-5f);

    float4 g  = *(const float4*)(gamma + lane * 4);
    float4 bt = *(const float4*)(beta + lane * 4);
    float4 o4;
    o4.x = dx * rstd * g.x + bt.x;
    o4.y = dy * rstd * g.y + bt.y;
    o4.z = dz * rstd * g.z + bt.z;
    o4.w = dw * rstd * g.w + bt.w;
    *(float4*)(out + (size_t)row * DIN + lane * 4) = o4;
}

// -----------------------------------------------------------------------------
extern "C" void kernel_launch(void* const* d_in, const int* in_sizes, int n_in,
                              void* d_out, int out_size) {
    const float* x     = (const float*)d_in[0];
    const void*  ei    = d_in[1];                 // int32 or int64, sniffed on device
    const float* ew    = (const float*)d_in[2];
    const float* W1    = (const float*)d_in[3];
    const float* b1    = (const float*)d_in[4];
    const float* W2    = (const float*)d_in[5];
    const float* b2    = (const float*)d_in[6];
    const float* gamma = (const float*)d_in[7];
    const float* beta  = (const float*)d_in[8];
    float*       out   = (float*)d_out;

    float *dinv, *agg1, *h, *p, *agg2;
    int *src, *dst;
    cudaGetSymbolAddress((void**)&dinv, g_dinv);
    cudaGetSymbolAddress((void**)&agg1, g_agg1);
    cudaGetSymbolAddress((void**)&h,    g_h);
    cudaGetSymbolAddress((void**)&p,    g_p);
    cudaGetSymbolAddress((void**)&agg2, g_agg2);
    cudaGetSymbolAddress((void**)&src,  g_src);
    cudaGetSymbolAddress((void**)&dst,  g_dst);

    const int n = NN, e = EE;

    // 0. sniff edge_index dtype, materialize clean int32 src/dst
    detect_idx_kernel<<<1, 128>>>((const int*)ei);
    convert_idx_kernel<<<(e + 255) / 256, 256>>>(ei, src, dst, e);

    // 1. degree (self-loops baked in as init to 1.0)
    init_deg_kernel<<<(n + 255) / 256, 256>>>(dinv, n);
    deg_accum_kernel<<<(e + 255) / 256, 256>>>(dst, ew, dinv, e);
    dinv_kernel<<<(n + 255) / 256, 256>>>(dinv, n);

    // 2. agg1 = A_norm @ x  (self-loop pass doubles as zero-init)
    selfloop_init_kernel<<<(n * DIN + 255) / 256, 256>>>(x, dinv, agg1, n * DIN);
    edge_scatter_kernel<<<(e * 32 + 255) / 256, 256>>>(src, dst, ew, dinv, x, agg1, e);

    // 3. h = relu(agg1 @ W1^T + b1)   [N x 256]
    {
        dim3 grid((n + 127) / 128, DH / 64);
        gemm_tn_kernel<<<grid, 256>>>(agg1, W1, b1, h, n, DIN, DH, 1);
    }

    // 4. p = h @ W2^T  [N x 128], bias deferred to LN
    {
        dim3 grid((n + 127) / 128, DIN / 64);
        gemm_tn_kernel<<<grid, 256>>>(h, W2, nullptr, p, n, DH, DIN, 0);
    }

    // 5. agg2 = A_norm @ p
    selfloop_init_kernel<<<(n * DIN + 255) / 256, 256>>>(p, dinv, agg2, n * DIN);
    edge_scatter_kernel<<<(e * 32 + 255) / 256, 256>>>(src, dst, ew, dinv, p, agg2, e);

    // 6. out = LN(agg2 + b2) * gamma + beta
    ln_kernel<<<(n * 32 + 255) / 256, 256>>>(agg2, b2, gamma, beta, out, n);
}